// round 1
// baseline (speedup 1.0000x reference)
#include <cuda_runtime.h>
#include <math.h>

#define Bd 4
#define Td 2048
#define Cd 1024
#define Hd 16
#define DHd 64

// Scratch (allocation-free rule: __device__ globals)
__device__ float g_qkv[(size_t)Bd * Td * 3 * Cd];   // [B*T, 3C]  ~100.7 MB
__device__ float g_y[(size_t)Bd * Td * Cd];         // [B*T, C]   ~33.6 MB

// ---------------------------------------------------------------------------
// SGEMM: C[M,N] = A[M,K] @ B[K,N], all row-major, M%128==0, N%128==0, K%8==0
// 128x128 tile, 256 threads, 8x8 per thread (2x2 quadrant split).
// ---------------------------------------------------------------------------
__global__ void __launch_bounds__(256) sgemm128x128(
    const float* __restrict__ A, const float* __restrict__ B,
    float* __restrict__ Cmat, int M, int N, int K)
{
    __shared__ float As[8][132];   // padded: conflict-free transposed stores
    __shared__ float Bs[8][128];

    const int tid = threadIdx.x;
    const int tx = tid & 15;      // 0..15 -> cols {tx*4..+3} and {64+tx*4..+3}
    const int ty = tid >> 4;      // 0..15 -> rows {ty*4..+3} and {64+ty*4..+3}
    const int row0 = blockIdx.y * 128;
    const int col0 = blockIdx.x * 128;

    const int a_row = tid >> 1;          // 0..127
    const int a_k   = (tid & 1) << 2;    // 0 or 4
    const int b_k   = tid >> 5;          // 0..7
    const int b_col = (tid & 31) << 2;   // 0..124

    const float* Ap = A + (size_t)(row0 + a_row) * K + a_k;
    const float* Bp = B + (size_t)b_k * N + col0 + b_col;

    float acc[8][8];
#pragma unroll
    for (int i = 0; i < 8; i++)
#pragma unroll
        for (int j = 0; j < 8; j++) acc[i][j] = 0.f;

    for (int k0 = 0; k0 < K; k0 += 8) {
        const float4 av = *(const float4*)(Ap + k0);
        const float4 bv = *(const float4*)(Bp + (size_t)k0 * N);
        __syncthreads();
        As[a_k + 0][a_row] = av.x;
        As[a_k + 1][a_row] = av.y;
        As[a_k + 2][a_row] = av.z;
        As[a_k + 3][a_row] = av.w;
        *(float4*)&Bs[b_k][b_col] = bv;
        __syncthreads();
#pragma unroll
        for (int kk = 0; kk < 8; kk++) {
            const float4 a0 = *(const float4*)&As[kk][ty * 4];
            const float4 a1 = *(const float4*)&As[kk][64 + ty * 4];
            const float4 b0 = *(const float4*)&Bs[kk][tx * 4];
            const float4 b1 = *(const float4*)&Bs[kk][64 + tx * 4];
            const float a[8]  = {a0.x, a0.y, a0.z, a0.w, a1.x, a1.y, a1.z, a1.w};
            const float bb[8] = {b0.x, b0.y, b0.z, b0.w, b1.x, b1.y, b1.z, b1.w};
#pragma unroll
            for (int i = 0; i < 8; i++)
#pragma unroll
                for (int j = 0; j < 8; j++)
                    acc[i][j] = fmaf(a[i], bb[j], acc[i][j]);
        }
    }

#pragma unroll
    for (int i = 0; i < 8; i++) {
        const int r = row0 + ((i < 4) ? (ty * 4 + i) : (64 + ty * 4 + (i - 4)));
        float* cp = Cmat + (size_t)r * N + col0;
        float4 v0 = make_float4(acc[i][0], acc[i][1], acc[i][2], acc[i][3]);
        float4 v1 = make_float4(acc[i][4], acc[i][5], acc[i][6], acc[i][7]);
        *(float4*)(cp + tx * 4) = v0;
        *(float4*)(cp + 64 + tx * 4) = v1;
    }
}

// ---------------------------------------------------------------------------
// Flash attention (causal), fp32.
// Grid: (T/64, B*H). Block: 256 threads.
// Thread (row = tid>>2, tx = tid&3): owns q-row `row` of the 64-row q-tile,
//   S columns j = jj*4+tx (16 of 64), O columns d = tx*16..tx*16+15.
// Q lives in registers; K/V 64x64 tiles in smem (stride 68).
// P broadcast within the 4-lane row-quad via shuffles (no smem P tile).
// ---------------------------------------------------------------------------
__global__ void __launch_bounds__(256) flash_attn(
    const float* __restrict__ qkv, float* __restrict__ y)
{
    __shared__ float Ks[64][68];
    __shared__ float Vs[64][68];

    const int tid  = threadIdx.x;
    const int row  = tid >> 2;
    const int tx   = tid & 3;
    const int lane = tid & 31;
    // heavy q-blocks first (qb large => more k-tiles) to reduce wave tail
    const int qb = gridDim.x - 1 - blockIdx.x;
    const int bh = blockIdx.y;
    const int b  = bh >> 4;   // H = 16
    const int h  = bh & 15;
    const int qi = qb * 64 + row;

    const size_t rs = 3 * Cd;  // qkv row stride

    // Q row -> registers (reused across all k-tiles)
    const float* qp = qkv + ((size_t)b * Td + qi) * rs + h * DHd;
    float4 qr[16];
#pragma unroll
    for (int i = 0; i < 16; i++) qr[i] = *(const float4*)(qp + i * 4);

    float o[16];
#pragma unroll
    for (int i = 0; i < 16; i++) o[i] = 0.f;
    float m_i = -1e30f, l_i = 0.f;

    const float* kb0 = qkv + ((size_t)b * Td) * rs + Cd + h * DHd;
    const float* vb0 = kb0 + Cd;

    for (int kb = 0; kb <= qb; kb++) {
        __syncthreads();
#pragma unroll
        for (int i = 0; i < 4; i++) {
            const int idx = tid + 256 * i;       // 0..1023
            const int r   = idx >> 4;            // 0..63
            const int c4  = (idx & 15) << 2;     // 0..60
            const size_t goff = ((size_t)kb * 64 + r) * rs + c4;
            *(float4*)&Ks[r][c4] = *(const float4*)(kb0 + goff);
            *(float4*)&Vs[r][c4] = *(const float4*)(vb0 + goff);
        }
        __syncthreads();

        // S = Q @ K^T for this thread's 16 columns (j = jj*4+tx)
        float s[16];
#pragma unroll
        for (int jj = 0; jj < 16; jj++) s[jj] = 0.f;
#pragma unroll
        for (int d4 = 0; d4 < 16; d4++) {
            const float4 qv = qr[d4];
#pragma unroll
            for (int jj = 0; jj < 16; jj++) {
                const float4 kv = *(const float4*)&Ks[jj * 4 + tx][d4 * 4];
                s[jj] = fmaf(qv.x, kv.x, s[jj]);
                s[jj] = fmaf(qv.y, kv.y, s[jj]);
                s[jj] = fmaf(qv.z, kv.z, s[jj]);
                s[jj] = fmaf(qv.w, kv.w, s[jj]);
            }
        }

        const float sc = 0.125f;  // 1/sqrt(64)
        if (kb == qb) {
#pragma unroll
            for (int jj = 0; jj < 16; jj++) {
                const int kj = kb * 64 + jj * 4 + tx;
                s[jj] = (kj > qi) ? -1e30f : s[jj] * sc;
            }
        } else {
#pragma unroll
            for (int jj = 0; jj < 16; jj++) s[jj] *= sc;
        }

        // row max over the 4-lane quad
        float mloc = s[0];
#pragma unroll
        for (int jj = 1; jj < 16; jj++) mloc = fmaxf(mloc, s[jj]);
        mloc = fmaxf(mloc, __shfl_xor_sync(0xffffffffu, mloc, 1));
        mloc = fmaxf(mloc, __shfl_xor_sync(0xffffffffu, mloc, 2));
        const float m_new = fmaxf(m_i, mloc);
        const float corr  = __expf(m_i - m_new);
        m_i = m_new;

        float lloc = 0.f;
#pragma unroll
        for (int jj = 0; jj < 16; jj++) {
            s[jj] = __expf(s[jj] - m_new);   // s becomes p
            lloc += s[jj];
        }
        lloc += __shfl_xor_sync(0xffffffffu, lloc, 1);
        lloc += __shfl_xor_sync(0xffffffffu, lloc, 2);
        l_i = l_i * corr + lloc;

#pragma unroll
        for (int dd = 0; dd < 16; dd++) o[dd] *= corr;

        // O += P @ V : gather p_j across the row-quad via shuffle
#pragma unroll
        for (int j = 0; j < 64; j++) {
            const float pj = __shfl_sync(0xffffffffu, s[j >> 2],
                                         (lane & ~3) | (j & 3));
            const float4 v0 = *(const float4*)&Vs[j][tx * 16 + 0];
            const float4 v1 = *(const float4*)&Vs[j][tx * 16 + 4];
            const float4 v2 = *(const float4*)&Vs[j][tx * 16 + 8];
            const float4 v3 = *(const float4*)&Vs[j][tx * 16 + 12];
            o[0]  = fmaf(pj, v0.x, o[0]);  o[1]  = fmaf(pj, v0.y, o[1]);
            o[2]  = fmaf(pj, v0.z, o[2]);  o[3]  = fmaf(pj, v0.w, o[3]);
            o[4]  = fmaf(pj, v1.x, o[4]);  o[5]  = fmaf(pj, v1.y, o[5]);
            o[6]  = fmaf(pj, v1.z, o[6]);  o[7]  = fmaf(pj, v1.w, o[7]);
            o[8]  = fmaf(pj, v2.x, o[8]);  o[9]  = fmaf(pj, v2.y, o[9]);
            o[10] = fmaf(pj, v2.z, o[10]); o[11] = fmaf(pj, v2.w, o[11]);
            o[12] = fmaf(pj, v3.x, o[12]); o[13] = fmaf(pj, v3.y, o[13]);
            o[14] = fmaf(pj, v3.z, o[14]); o[15] = fmaf(pj, v3.w, o[15]);
        }
    }

    const float inv = 1.f / l_i;
    float* yp = y + ((size_t)b * Td + qi) * Cd + h * DHd + tx * 16;
    *(float4*)(yp + 0)  = make_float4(o[0] * inv,  o[1] * inv,  o[2] * inv,  o[3] * inv);
    *(float4*)(yp + 4)  = make_float4(o[4] * inv,  o[5] * inv,  o[6] * inv,  o[7] * inv);
    *(float4*)(yp + 8)  = make_float4(o[8] * inv,  o[9] * inv,  o[10] * inv, o[11] * inv);
    *(float4*)(yp + 12) = make_float4(o[12] * inv, o[13] * inv, o[14] * inv, o[15] * inv);
}

// ---------------------------------------------------------------------------
extern "C" void kernel_launch(void* const* d_in, const int* in_sizes, int n_in,
                              void* d_out, int out_size)
{
    const float* x      = (const float*)d_in[0];   // [B,T,C]
    const float* w_attn = (const float*)d_in[1];   // [C,3C]
    const float* w_proj = (const float*)d_in[2];   // [C,C]
    float* out = (float*)d_out;                    // [B,T,C]

    float *qkv, *y;
    cudaGetSymbolAddress((void**)&qkv, g_qkv);
    cudaGetSymbolAddress((void**)&y, g_y);

    // 1) QKV GEMM: [8192,1024] @ [1024,3072]
    dim3 g1(3 * Cd / 128, (Bd * Td) / 128);   // (24, 64)
    sgemm128x128<<<g1, 256>>>(x, w_attn, qkv, Bd * Td, 3 * Cd, Cd);

    // 2) causal flash attention -> y [B,T,C]
    dim3 g2(Td / 64, Bd * Hd);                // (32, 64)
    flash_attn<<<g2, 256>>>(qkv, y);

    // 3) proj GEMM: [8192,1024] @ [1024,1024]
    dim3 g3(Cd / 128, (Bd * Td) / 128);       // (8, 64)
    sgemm128x128<<<g3, 256>>>(y, w_proj, out, Bd * Td, Cd, Cd);
}

// round 2
// speedup vs baseline: 1.0171x; 1.0171x over previous
#include <cuda_runtime.h>
#include <math.h>

#define Bd 4
#define Td 2048
#define Cd 1024
#define Hd 16
#define DHd 64

// Scratch (allocation-free rule: __device__ globals)
__device__ float g_qkv[(size_t)Bd * Td * 3 * Cd];   // [B*T, 3C]
__device__ float g_y[(size_t)Bd * Td * Cd];         // [B*T, C]

typedef unsigned long long u64;

// ---- packed f32x2 helpers (sm_100+ PTX; SASS FFMA2/FMUL2) ------------------
__device__ __forceinline__ u64 fma2(u64 a, u64 b, u64 c) {
    u64 d;
    asm("fma.rn.f32x2 %0, %1, %2, %3;" : "=l"(d) : "l"(a), "l"(b), "l"(c));
    return d;
}
__device__ __forceinline__ u64 mul2(u64 a, u64 b) {
    u64 d;
    asm("mul.rn.f32x2 %0, %1, %2;" : "=l"(d) : "l"(a), "l"(b));
    return d;
}
__device__ __forceinline__ u64 pack2(float lo, float hi) {
    u64 d;
    asm("mov.b64 %0, {%1, %2};" : "=l"(d) : "f"(lo), "f"(hi));
    return d;
}
__device__ __forceinline__ float2 unpack2(u64 v) {
    float lo, hi;
    asm("mov.b64 {%0, %1}, %2;" : "=f"(lo), "=f"(hi) : "l"(v));
    return make_float2(lo, hi);
}

// ---------------------------------------------------------------------------
// SGEMM: C[M,N] = A[M,K] @ B[K,N], row-major, M%128==0, N%128==0, K%8==0
// 128x128 tile, 256 threads, 8x8 per thread (2x2 quadrant split), f32x2 core.
// ---------------------------------------------------------------------------
__global__ void __launch_bounds__(256) sgemm128x128(
    const float* __restrict__ A, const float* __restrict__ B,
    float* __restrict__ Cmat, int M, int N, int K)
{
    __shared__ float As[8][132];
    __shared__ float Bs[8][128];

    const int tid = threadIdx.x;
    const int tx = tid & 15;
    const int ty = tid >> 4;
    const int row0 = blockIdx.y * 128;
    const int col0 = blockIdx.x * 128;

    const int a_row = tid >> 1;
    const int a_k   = (tid & 1) << 2;
    const int b_k   = tid >> 5;
    const int b_col = (tid & 31) << 2;

    const float* Ap = A + (size_t)(row0 + a_row) * K + a_k;
    const float* Bp = B + (size_t)b_k * N + col0 + b_col;

    // acc2[i][p]: row i, column pair p (p<2 -> cols tx*4+2p.., p>=2 -> 64+tx*4+..)
    u64 acc2[8][4];
#pragma unroll
    for (int i = 0; i < 8; i++)
#pragma unroll
        for (int j = 0; j < 4; j++) acc2[i][j] = 0ull;

    for (int k0 = 0; k0 < K; k0 += 8) {
        const float4 av = *(const float4*)(Ap + k0);
        const float4 bv = *(const float4*)(Bp + (size_t)k0 * N);
        __syncthreads();
        As[a_k + 0][a_row] = av.x;
        As[a_k + 1][a_row] = av.y;
        As[a_k + 2][a_row] = av.z;
        As[a_k + 3][a_row] = av.w;
        *(float4*)&Bs[b_k][b_col] = bv;
        __syncthreads();
#pragma unroll
        for (int kk = 0; kk < 8; kk++) {
            const float4 a0 = *(const float4*)&As[kk][ty * 4];
            const float4 a1 = *(const float4*)&As[kk][64 + ty * 4];
            const float a[8] = {a0.x, a0.y, a0.z, a0.w, a1.x, a1.y, a1.z, a1.w};
            const u64* bp0 = (const u64*)&Bs[kk][tx * 4];        // 2 pairs
            const u64* bp1 = (const u64*)&Bs[kk][64 + tx * 4];   // 2 pairs
            const u64 bp[4] = {bp0[0], bp0[1], bp1[0], bp1[1]};
#pragma unroll
            for (int i = 0; i < 8; i++) {
                const u64 ad = pack2(a[i], a[i]);
#pragma unroll
                for (int j = 0; j < 4; j++)
                    acc2[i][j] = fma2(ad, bp[j], acc2[i][j]);
            }
        }
    }

#pragma unroll
    for (int i = 0; i < 8; i++) {
        const int r = row0 + ((i < 4) ? (ty * 4 + i) : (64 + ty * 4 + (i - 4)));
        float* cp = Cmat + (size_t)r * N + col0;
        const float2 c0 = unpack2(acc2[i][0]);
        const float2 c1 = unpack2(acc2[i][1]);
        const float2 c2 = unpack2(acc2[i][2]);
        const float2 c3 = unpack2(acc2[i][3]);
        *(float4*)(cp + tx * 4)      = make_float4(c0.x, c0.y, c1.x, c1.y);
        *(float4*)(cp + 64 + tx * 4) = make_float4(c2.x, c2.y, c3.x, c3.y);
    }
}

// ---------------------------------------------------------------------------
// Flash attention (causal), fp32, f32x2 core.
// Grid: (T/64, B*H). Block: 256. Thread (row=tid>>2, tx=tid&3):
//   q-row `row`, S columns j = jj*4+tx (16 of 64), O columns d = tx*16..+15.
// ---------------------------------------------------------------------------
__global__ void __launch_bounds__(256) flash_attn(
    const float* __restrict__ qkv, float* __restrict__ y)
{
    __shared__ float Ks[64][68];
    __shared__ float Vs[64][68];

    const int tid  = threadIdx.x;
    const int row  = tid >> 2;
    const int tx   = tid & 3;
    const int lane = tid & 31;
    const int qb = gridDim.x - 1 - blockIdx.x;   // heavy q-blocks first
    const int bh = blockIdx.y;
    const int b  = bh >> 4;
    const int h  = bh & 15;
    const int qi = qb * 64 + row;

    const size_t rs = 3 * Cd;

    const float* qp = qkv + ((size_t)b * Td + qi) * rs + h * DHd;
    float4 qr[16];
#pragma unroll
    for (int i = 0; i < 16; i++) qr[i] = *(const float4*)(qp + i * 4);
    const u64* q2 = (const u64*)qr;   // 32 packed d-pairs

    u64 o2[8];
#pragma unroll
    for (int i = 0; i < 8; i++) o2[i] = 0ull;
    float m_i = -1e30f, l_i = 0.f;

    const float* kb0 = qkv + ((size_t)b * Td) * rs + Cd + h * DHd;
    const float* vb0 = kb0 + Cd;

    for (int kb = 0; kb <= qb; kb++) {
        __syncthreads();
#pragma unroll
        for (int i = 0; i < 4; i++) {
            const int idx = tid + 256 * i;
            const int r   = idx >> 4;
            const int c4  = (idx & 15) << 2;
            const size_t goff = ((size_t)kb * 64 + r) * rs + c4;
            *(float4*)&Ks[r][c4] = *(const float4*)(kb0 + goff);
            *(float4*)&Vs[r][c4] = *(const float4*)(vb0 + goff);
        }
        __syncthreads();

        // S = Q @ K^T : accumulate even/odd d in packed lanes
        u64 s2[16];
#pragma unroll
        for (int jj = 0; jj < 16; jj++) s2[jj] = 0ull;
#pragma unroll
        for (int d4 = 0; d4 < 16; d4++) {
            const u64 qa = q2[d4 * 2];
            const u64 qb2 = q2[d4 * 2 + 1];
#pragma unroll
            for (int jj = 0; jj < 16; jj++) {
                float4 kv = *(const float4*)&Ks[jj * 4 + tx][d4 * 4];
                const u64* kp = (const u64*)&kv;
                s2[jj] = fma2(qa, kp[0], s2[jj]);
                s2[jj] = fma2(qb2, kp[1], s2[jj]);
            }
        }
        float s[16];
#pragma unroll
        for (int jj = 0; jj < 16; jj++) {
            const float2 t = unpack2(s2[jj]);
            s[jj] = t.x + t.y;
        }

        const float sc = 0.125f;  // 1/sqrt(64)
        if (kb == qb) {
#pragma unroll
            for (int jj = 0; jj < 16; jj++) {
                const int kj = kb * 64 + jj * 4 + tx;
                s[jj] = (kj > qi) ? -1e30f : s[jj] * sc;
            }
        } else {
#pragma unroll
            for (int jj = 0; jj < 16; jj++) s[jj] *= sc;
        }

        float mloc = s[0];
#pragma unroll
        for (int jj = 1; jj < 16; jj++) mloc = fmaxf(mloc, s[jj]);
        mloc = fmaxf(mloc, __shfl_xor_sync(0xffffffffu, mloc, 1));
        mloc = fmaxf(mloc, __shfl_xor_sync(0xffffffffu, mloc, 2));
        const float m_new = fmaxf(m_i, mloc);
        const float corr  = __expf(m_i - m_new);
        m_i = m_new;

        float lloc = 0.f;
#pragma unroll
        for (int jj = 0; jj < 16; jj++) {
            s[jj] = __expf(s[jj] - m_new);
            lloc += s[jj];
        }
        lloc += __shfl_xor_sync(0xffffffffu, lloc, 1);
        lloc += __shfl_xor_sync(0xffffffffu, lloc, 2);
        l_i = l_i * corr + lloc;

        const u64 corr2 = pack2(corr, corr);
#pragma unroll
        for (int p = 0; p < 8; p++) o2[p] = mul2(o2[p], corr2);

        // O += P @ V
#pragma unroll
        for (int j = 0; j < 64; j++) {
            const float pj = __shfl_sync(0xffffffffu, s[j >> 2],
                                         (lane & ~3) | (j & 3));
            const u64 pj2 = pack2(pj, pj);
            float4 v0 = *(const float4*)&Vs[j][tx * 16 + 0];
            float4 v1 = *(const float4*)&Vs[j][tx * 16 + 4];
            float4 v2 = *(const float4*)&Vs[j][tx * 16 + 8];
            float4 v3 = *(const float4*)&Vs[j][tx * 16 + 12];
            const u64* vp0 = (const u64*)&v0;
            const u64* vp1 = (const u64*)&v1;
            const u64* vp2 = (const u64*)&v2;
            const u64* vp3 = (const u64*)&v3;
            o2[0] = fma2(pj2, vp0[0], o2[0]);
            o2[1] = fma2(pj2, vp0[1], o2[1]);
            o2[2] = fma2(pj2, vp1[0], o2[2]);
            o2[3] = fma2(pj2, vp1[1], o2[3]);
            o2[4] = fma2(pj2, vp2[0], o2[4]);
            o2[5] = fma2(pj2, vp2[1], o2[5]);
            o2[6] = fma2(pj2, vp3[0], o2[6]);
            o2[7] = fma2(pj2, vp3[1], o2[7]);
        }
    }

    const float inv = 1.f / l_i;
    const u64 inv2 = pack2(inv, inv);
    float ov[16];
#pragma unroll
    for (int p = 0; p < 8; p++) {
        const float2 t = unpack2(mul2(o2[p], inv2));
        ov[2 * p]     = t.x;
        ov[2 * p + 1] = t.y;
    }
    float* yp = y + ((size_t)b * Td + qi) * Cd + h * DHd + tx * 16;
    *(float4*)(yp + 0)  = make_float4(ov[0],  ov[1],  ov[2],  ov[3]);
    *(float4*)(yp + 4)  = make_float4(ov[4],  ov[5],  ov[6],  ov[7]);
    *(float4*)(yp + 8)  = make_float4(ov[8],  ov[9],  ov[10], ov[11]);
    *(float4*)(yp + 12) = make_float4(ov[12], ov[13], ov[14], ov[15]);
}

// ---------------------------------------------------------------------------
extern "C" void kernel_launch(void* const* d_in, const int* in_sizes, int n_in,
                              void* d_out, int out_size)
{
    const float* x      = (const float*)d_in[0];
    const float* w_attn = (const float*)d_in[1];
    const float* w_proj = (const float*)d_in[2];
    float* out = (float*)d_out;

    float *qkv, *yv;
    cudaGetSymbolAddress((void**)&qkv, g_qkv);
    cudaGetSymbolAddress((void**)&yv, g_y);

    dim3 g1(3 * Cd / 128, (Bd * Td) / 128);
    sgemm128x128<<<g1, 256>>>(x, w_attn, qkv, Bd * Td, 3 * Cd, Cd);

    dim3 g2(Td / 64, Bd * Hd);
    flash_attn<<<g2, 256>>>(qkv, yv);

    dim3 g3(Cd / 128, (Bd * Td) / 128);
    sgemm128x128<<<g3, 256>>>(yv, w_proj, out, Bd * Td, Cd, Cd);
}

// round 4
// speedup vs baseline: 4.5307x; 4.4543x over previous
#include <cuda_runtime.h>
#include <cuda_bf16.h>
#include <math.h>
#include <stdint.h>

#define Bd 4
#define Td 2048
#define Cd 1024
#define Hd 16
#define DHd 64
#define Mtot (Bd * Td)      // 8192
#define K3 (3 * Cd)         // 3072 split-K: A=[hi|hi|lo], B=[hi|lo|hi]

typedef uint32_t u32;

// ---- scratch (__device__ globals; allocation-free rule) --------------------
__device__ float g_qkv[(size_t)Mtot * 3 * Cd];                 // fp32 [8192,3072]
__device__ __nv_bfloat16 g_x3[(size_t)Mtot * K3];              // [8192,3072]
__device__ __nv_bfloat16 g_y3[(size_t)Mtot * K3];              // [8192,3072]
__device__ __nv_bfloat16 g_wa3[(size_t)(3 * Cd) * K3];         // [3072,3072]
__device__ __nv_bfloat16 g_wp3[(size_t)Cd * K3];               // [1024,3072]
// attention operands, per (b,h): Q/K [bh][t][64], Vt [bh][d][t]
__device__ __nv_bfloat16 g_qhi[(size_t)Bd * Hd * Td * DHd];
__device__ __nv_bfloat16 g_qlo[(size_t)Bd * Hd * Td * DHd];
__device__ __nv_bfloat16 g_khi[(size_t)Bd * Hd * Td * DHd];
__device__ __nv_bfloat16 g_klo[(size_t)Bd * Hd * Td * DHd];
__device__ __nv_bfloat16 g_vthi[(size_t)Bd * Hd * DHd * Td];
__device__ __nv_bfloat16 g_vtlo[(size_t)Bd * Hd * DHd * Td];

// ---- helpers ----------------------------------------------------------------
__device__ __forceinline__ u32 smem_u32(const void* p) {
    u32 a;
    asm("{ .reg .u64 t; cvta.to.shared.u64 t, %1; cvt.u32.u64 %0, t; }" : "=r"(a) : "l"(p));
    return a;
}
__device__ __forceinline__ void ldm4(u32& r0, u32& r1, u32& r2, u32& r3, u32 addr) {
    asm volatile("ldmatrix.sync.aligned.m8n8.x4.shared.b16 {%0,%1,%2,%3}, [%4];"
                 : "=r"(r0), "=r"(r1), "=r"(r2), "=r"(r3) : "r"(addr));
}
__device__ __forceinline__ void mma16816(float* d, const u32* a, u32 b0, u32 b1) {
    asm volatile(
        "mma.sync.aligned.m16n8k16.row.col.f32.bf16.bf16.f32 "
        "{%0,%1,%2,%3}, {%4,%5,%6,%7}, {%8,%9}, {%0,%1,%2,%3};"
        : "+f"(d[0]), "+f"(d[1]), "+f"(d[2]), "+f"(d[3])
        : "r"(a[0]), "r"(a[1]), "r"(a[2]), "r"(a[3]), "r"(b0), "r"(b1));
}
// pack: upper half = hi, lower half = lo
__device__ __forceinline__ u32 cvt_bf16x2(float hi, float lo) {
    u32 r;
    asm("cvt.rn.bf16x2.f32 %0, %1, %2;" : "=r"(r) : "f"(hi), "f"(lo));
    return r;
}
__device__ __forceinline__ float bf_lo(u32 r) { return __uint_as_float(r << 16); }
__device__ __forceinline__ float bf_hi(u32 r) { return __uint_as_float(r & 0xFFFF0000u); }

// FFMA-only exp (rel err ~1e-7), valid for x <= 0
__device__ __forceinline__ float fexp(float x) {
    x = fmaxf(x, -80.f);
    float t  = fmaf(x, 1.4426950408889634f, 12582912.0f);
    float fi = t - 12582912.0f;
    float f  = fmaf(x, 1.4426950408889634f, -fi);   // in [-0.5, 0.5]
    float p  = 0.00015403530393381609f;
    p = fmaf(p, f, 0.0013333558146428443f);
    p = fmaf(p, f, 0.009618129107628477f);
    p = fmaf(p, f, 0.05550410866482158f);
    p = fmaf(p, f, 0.2402265069591007f);
    p = fmaf(p, f, 0.6931471805599453f);
    p = fmaf(p, f, 1.0f);
    int ei = __float_as_int(t) - 0x4B400000;
    return __uint_as_float(__float_as_int(p) + (ei << 23));
}

// ---------------------------------------------------------------------------
// fp32 -> bf16x3 split conversions (as in R3)
// ---------------------------------------------------------------------------
__global__ void split_rows3(const float* __restrict__ in, __nv_bfloat16* __restrict__ out,
                            int R, int Cc)
{
    int idx = blockIdx.x * blockDim.x + threadIdx.x;
    int total = R * Cc / 4;
    if (idx >= total) return;
    int c = (idx % (Cc / 4)) * 4;
    int r = idx / (Cc / 4);
    float4 v = *(const float4*)(in + (size_t)r * Cc + c);
    __nv_bfloat162 h0 = __floats2bfloat162_rn(v.x, v.y);
    __nv_bfloat162 h1 = __floats2bfloat162_rn(v.z, v.w);
    __nv_bfloat162 l0 = __floats2bfloat162_rn(v.x - __bfloat162float(h0.x),
                                              v.y - __bfloat162float(h0.y));
    __nv_bfloat162 l1 = __floats2bfloat162_rn(v.z - __bfloat162float(h1.x),
                                              v.w - __bfloat162float(h1.y));
    __nv_bfloat16* o = out + (size_t)r * (3 * Cc) + c;
    uint2 hv = make_uint2(*(u32*)&h0, *(u32*)&h1);
    uint2 lv = make_uint2(*(u32*)&l0, *(u32*)&l1);
    *(uint2*)(o)          = hv;
    *(uint2*)(o + Cc)     = hv;
    *(uint2*)(o + 2 * Cc) = lv;
}

__global__ void split_tr3(const float* __restrict__ w, __nv_bfloat16* __restrict__ out,
                          int K, int N)
{
    int idx = blockIdx.x * blockDim.x + threadIdx.x;
    if (idx >= K * N) return;
    int n = idx / K;
    int k = idx % K;
    float v = w[(size_t)k * N + n];
    __nv_bfloat16 hi = __float2bfloat16(v);
    __nv_bfloat16 lo = __float2bfloat16(v - __bfloat162float(hi));
    __nv_bfloat16* o = out + (size_t)n * (3 * K);
    o[k]         = hi;
    o[K + k]     = lo;
    o[2 * K + k] = hi;
}

// ---------------------------------------------------------------------------
// GEMM (HMMA): C[M,Nout] fp32 = A3[M,3072] @ Bt3[Nout,3072]^T
// CTA 128x128, 8 warps (4m x 2n), warp 32x64. KC=64, double-buffered.
// smem rows padded to 72 bf16 (144B) -> conflict-free ldmatrix.
// ---------------------------------------------------------------------------
#define GST 72
#define GBUF (128 * GST)             // bf16 elems per buffer
__global__ void __launch_bounds__(256) gemm_mma(
    const __nv_bfloat16* __restrict__ A, const __nv_bfloat16* __restrict__ Bt,
    float* __restrict__ C, int Nout)
{
    extern __shared__ __align__(16) __nv_bfloat16 sm[];
    __nv_bfloat16* As = sm;                 // [2][128][72]
    __nv_bfloat16* Bs = sm + 2 * GBUF;      // [2][128][72]
    const u32 sA = smem_u32(As), sB = smem_u32(Bs);

    const int tid = threadIdx.x, wid = tid >> 5, lane = tid & 31;
    const int wm = wid >> 1, wn = wid & 1;
    const int g = lane >> 2, t = lane & 3;
    const int row0 = blockIdx.y * 128, col0 = blockIdx.x * 128;

    // global load mapping: 4 uint4 per thread per chunk
    const int lr = tid >> 3, lc = (tid & 7) * 8;
    const __nv_bfloat16* Ag = A + (size_t)(row0 + lr) * K3 + lc;
    const __nv_bfloat16* Bg = Bt + (size_t)(col0 + lr) * K3 + lc;

    float acc[2][8][4];
#pragma unroll
    for (int i = 0; i < 2; i++)
#pragma unroll
        for (int j = 0; j < 8; j++)
#pragma unroll
            for (int r = 0; r < 4; r++) acc[i][j][r] = 0.f;

    // ldmatrix addresses (byte offsets within a buffer)
    const int a_row_off = (32 * wm + (lane & 15)) * 144 + ((lane >> 4) << 4);
    const int b_row_off = (64 * wn + (lane & 7) + 8 * ((lane >> 4) & 1)) * 144
                        + 16 * ((lane >> 3) & 1);

    uint4 pa[4], pb[4];
#pragma unroll
    for (int i = 0; i < 4; i++) {
        pa[i] = *(const uint4*)(Ag + (size_t)(32 * i) * K3);
        pb[i] = *(const uint4*)(Bg + (size_t)(32 * i) * K3);
    }
#pragma unroll
    for (int i = 0; i < 4; i++) {
        *(uint4*)(As + (lr + 32 * i) * GST + lc) = pa[i];
        *(uint4*)(Bs + (lr + 32 * i) * GST + lc) = pb[i];
    }

    for (int kc = 0; kc < 48; kc++) {
        __syncthreads();
        if (kc < 47) {
#pragma unroll
            for (int i = 0; i < 4; i++) {
                pa[i] = *(const uint4*)(Ag + (size_t)(32 * i) * K3 + (kc + 1) * 64);
                pb[i] = *(const uint4*)(Bg + (size_t)(32 * i) * K3 + (kc + 1) * 64);
            }
        }
        const int buf = kc & 1;
        const u32 abase = sA + buf * (GBUF * 2) + a_row_off;
        const u32 bbase = sB + buf * (GBUF * 2) + b_row_off;
#pragma unroll
        for (int kt = 0; kt < 4; kt++) {
            u32 af[2][4];
            ldm4(af[0][0], af[0][1], af[0][2], af[0][3], abase + kt * 32);
            ldm4(af[1][0], af[1][1], af[1][2], af[1][3], abase + 16 * 144 + kt * 32);
#pragma unroll
            for (int np = 0; np < 4; np++) {
                u32 b0, b1, b2, b3;
                ldm4(b0, b1, b2, b3, bbase + np * (16 * 144) + kt * 32);
                mma16816(acc[0][2 * np],     af[0], b0, b1);
                mma16816(acc[0][2 * np + 1], af[0], b2, b3);
                mma16816(acc[1][2 * np],     af[1], b0, b1);
                mma16816(acc[1][2 * np + 1], af[1], b2, b3);
            }
        }
        if (kc < 47) {
            const int nb = (kc + 1) & 1;
#pragma unroll
            for (int i = 0; i < 4; i++) {
                *(uint4*)(As + nb * GBUF + (lr + 32 * i) * GST + lc) = pa[i];
                *(uint4*)(Bs + nb * GBUF + (lr + 32 * i) * GST + lc) = pb[i];
            }
        }
    }

    // epilogue
#pragma unroll
    for (int mt = 0; mt < 2; mt++) {
        const int r0 = row0 + 32 * wm + 16 * mt + g;
#pragma unroll
        for (int nt = 0; nt < 8; nt++) {
            const int col = col0 + 64 * wn + 8 * nt + 2 * t;
            *(float2*)(C + (size_t)r0 * Nout + col)       = make_float2(acc[mt][nt][0], acc[mt][nt][1]);
            *(float2*)(C + (size_t)(r0 + 8) * Nout + col) = make_float2(acc[mt][nt][2], acc[mt][nt][3]);
        }
    }
}

// ---------------------------------------------------------------------------
// prep_attn: g_qkv fp32 -> Qhi/Qlo/Khi/Klo [bh][t][64] (Q pre-scaled by 1/8),
//            Vthi/Vtlo [bh][d][t] (transposed via smem).
// grid (T/64, B*H), 256 threads.
// ---------------------------------------------------------------------------
__global__ void __launch_bounds__(256) prep_attn(const float* __restrict__ qkv)
{
    __shared__ __nv_bfloat16 tvhi[64][72];
    __shared__ __nv_bfloat16 tvlo[64][72];
    const int tid = threadIdx.x;
    const int tb = blockIdx.x, bh = blockIdx.y;
    const int b = bh >> 4, h = bh & 15;

#pragma unroll
    for (int i = 0; i < 4; i++) {
        const int u = tid + 256 * i;       // 0..1023
        const int tr = u >> 4;             // 0..63
        const int d4 = (u & 15) * 4;
        const int tg = tb * 64 + tr;
        const size_t base = ((size_t)(b * Td + tg)) * 3072 + h * 64 + d4;
        float4 q = *(const float4*)(qkv + base);
        float4 k = *(const float4*)(qkv + base + 1024);
        float4 v = *(const float4*)(qkv + base + 2048);
        q.x *= 0.125f; q.y *= 0.125f; q.z *= 0.125f; q.w *= 0.125f;

        const size_t qidx = ((size_t)bh * Td + tg) * 64 + d4;
        __nv_bfloat162 qh0 = __floats2bfloat162_rn(q.x, q.y);
        __nv_bfloat162 qh1 = __floats2bfloat162_rn(q.z, q.w);
        __nv_bfloat162 ql0 = __floats2bfloat162_rn(q.x - __bfloat162float(qh0.x), q.y - __bfloat162float(qh0.y));
        __nv_bfloat162 ql1 = __floats2bfloat162_rn(q.z - __bfloat162float(qh1.x), q.w - __bfloat162float(qh1.y));
        *(uint2*)(g_qhi + qidx) = make_uint2(*(u32*)&qh0, *(u32*)&qh1);
        *(uint2*)(g_qlo + qidx) = make_uint2(*(u32*)&ql0, *(u32*)&ql1);

        __nv_bfloat162 kh0 = __floats2bfloat162_rn(k.x, k.y);
        __nv_bfloat162 kh1 = __floats2bfloat162_rn(k.z, k.w);
        __nv_bfloat162 kl0 = __floats2bfloat162_rn(k.x - __bfloat162float(kh0.x), k.y - __bfloat162float(kh0.y));
        __nv_bfloat162 kl1 = __floats2bfloat162_rn(k.z - __bfloat162float(kh1.x), k.w - __bfloat162float(kh1.y));
        *(uint2*)(g_khi + qidx) = make_uint2(*(u32*)&kh0, *(u32*)&kh1);
        *(uint2*)(g_klo + qidx) = make_uint2(*(u32*)&kl0, *(u32*)&kl1);

        float vv[4] = {v.x, v.y, v.z, v.w};
#pragma unroll
        for (int j = 0; j < 4; j++) {
            __nv_bfloat16 hi = __float2bfloat16(vv[j]);
            __nv_bfloat16 lo = __float2bfloat16(vv[j] - __bfloat162float(hi));
            tvhi[d4 + j][tr] = hi;
            tvlo[d4 + j][tr] = lo;
        }
    }
    __syncthreads();
#pragma unroll
    for (int i = 0; i < 2; i++) {
        const int u = tid + 256 * i;       // 0..511
        const int d = u >> 3;              // 0..63
        const int tc = (u & 7) * 8;
        const size_t vidx = ((size_t)bh * 64 + d) * Td + tb * 64 + tc;
        *(uint4*)(g_vthi + vidx) = *(uint4*)&tvhi[d][tc];
        *(uint4*)(g_vtlo + vidx) = *(uint4*)&tvlo[d][tc];
    }
}

// ---------------------------------------------------------------------------
// flash_mma: causal attention, HMMA bf16 hi/lo split. 128 threads, 4 warps.
// CTA = (64 q-rows, bh). Writes y3 = [hi|hi|lo] bf16 rows for proj GEMM.
// ---------------------------------------------------------------------------
__global__ void __launch_bounds__(128) flash_mma(__nv_bfloat16* __restrict__ y3)
{
    __shared__ __align__(16) __nv_bfloat16 s_t[4][64 * 72];   // khi, klo, vhi, vlo
    const int tid = threadIdx.x, wid = tid >> 5, lane = tid & 31;
    const int g = lane >> 2, t = lane & 3;
    const int qb = gridDim.x - 1 - blockIdx.x;   // heavy blocks first
    const int bh = blockIdx.y;
    const int b = bh >> 4, h = bh & 15;

    const size_t qkbase = (size_t)bh * Td * 64;
    const size_t vtbase = (size_t)bh * 64 * Td;

    const u32 s0 = smem_u32(s_t);
    const u32 sKhi = s0, sKlo = s0 + 9216, sVhi = s0 + 18432, sVlo = s0 + 27648;

    const int a_off = (16 * wid + (lane & 15)) * 144 + ((lane >> 4) << 4);
    const int b_off = ((lane & 7) + 8 * ((lane >> 4) & 1)) * 144 + 16 * ((lane >> 3) & 1);

    // ---- load Q tile into smem (reuse khi/klo buffers), ldmatrix to regs ----
#pragma unroll
    for (int i = 0; i < 4; i++) {
        const int u = tid + 128 * i;       // 0..511
        const int r = u >> 3, c = (u & 7) * 8;
        const size_t gq = qkbase + (size_t)(qb * 64 + r) * 64 + c;
        *(uint4*)&s_t[0][r * 72 + c] = *(const uint4*)(g_qhi + gq);
        *(uint4*)&s_t[1][r * 72 + c] = *(const uint4*)(g_qlo + gq);
    }
    __syncthreads();
    u32 qh[4][4], ql[4][4];
#pragma unroll
    for (int kt = 0; kt < 4; kt++) {
        ldm4(qh[kt][0], qh[kt][1], qh[kt][2], qh[kt][3], sKhi + a_off + kt * 32);
        ldm4(ql[kt][0], ql[kt][1], ql[kt][2], ql[kt][3], sKlo + a_off + kt * 32);
    }

    float o[8][4];
#pragma unroll
    for (int j = 0; j < 8; j++)
#pragma unroll
        for (int r = 0; r < 4; r++) o[j][r] = 0.f;
    float m0 = -1e30f, m1 = -1e30f, l0 = 0.f, l1 = 0.f;

    for (int kb = 0; kb <= qb; kb++) {
        __syncthreads();
#pragma unroll
        for (int i = 0; i < 4; i++) {
            const int u = tid + 128 * i;
            const int r = u >> 3, c = (u & 7) * 8;
            const size_t gk = qkbase + (size_t)(kb * 64 + r) * 64 + c;
            const size_t gv = vtbase + (size_t)r * Td + kb * 64 + c;
            *(uint4*)&s_t[0][r * 72 + c] = *(const uint4*)(g_khi + gk);
            *(uint4*)&s_t[1][r * 72 + c] = *(const uint4*)(g_klo + gk);
            *(uint4*)&s_t[2][r * 72 + c] = *(const uint4*)(g_vthi + gv);
            *(uint4*)&s_t[3][r * 72 + c] = *(const uint4*)(g_vtlo + gv);
        }
        __syncthreads();

        // ---- S = Qhi*Khi + Qhi*Klo + Qlo*Khi ----
        float s[8][4];
#pragma unroll
        for (int j = 0; j < 8; j++)
#pragma unroll
            for (int r = 0; r < 4; r++) s[j][r] = 0.f;
#pragma unroll
        for (int np = 0; np < 4; np++) {
#pragma unroll
            for (int kt = 0; kt < 4; kt++) {
                const int off = b_off + np * (16 * 144) + kt * 32;
                u32 h0, h1, h2, h3, e0, e1, e2, e3;
                ldm4(h0, h1, h2, h3, sKhi + off);
                mma16816(s[2 * np],     qh[kt], h0, h1);
                mma16816(s[2 * np + 1], qh[kt], h2, h3);
                mma16816(s[2 * np],     ql[kt], h0, h1);
                mma16816(s[2 * np + 1], ql[kt], h2, h3);
                ldm4(e0, e1, e2, e3, sKlo + off);
                mma16816(s[2 * np],     qh[kt], e0, e1);
                mma16816(s[2 * np + 1], qh[kt], e2, e3);
            }
        }

        // ---- mask (diagonal tile) ----
        if (kb == qb) {
            const int qg0 = qb * 64 + 16 * wid + g;
            const int qg1 = qg0 + 8;
#pragma unroll
            for (int nt = 0; nt < 8; nt++) {
                const int kg = kb * 64 + 8 * nt + 2 * t;
                if (kg > qg0)     s[nt][0] = -1e30f;
                if (kg + 1 > qg0) s[nt][1] = -1e30f;
                if (kg > qg1)     s[nt][2] = -1e30f;
                if (kg + 1 > qg1) s[nt][3] = -1e30f;
            }
        }

        // ---- online softmax ----
        float ml0 = -1e30f, ml1 = -1e30f;
#pragma unroll
        for (int nt = 0; nt < 8; nt++) {
            ml0 = fmaxf(ml0, fmaxf(s[nt][0], s[nt][1]));
            ml1 = fmaxf(ml1, fmaxf(s[nt][2], s[nt][3]));
        }
        ml0 = fmaxf(ml0, __shfl_xor_sync(0xffffffffu, ml0, 1));
        ml0 = fmaxf(ml0, __shfl_xor_sync(0xffffffffu, ml0, 2));
        ml1 = fmaxf(ml1, __shfl_xor_sync(0xffffffffu, ml1, 1));
        ml1 = fmaxf(ml1, __shfl_xor_sync(0xffffffffu, ml1, 2));
        const float mn0 = fmaxf(m0, ml0), mn1 = fmaxf(m1, ml1);
        const float cr0 = fexp(m0 - mn0), cr1 = fexp(m1 - mn1);
        m0 = mn0; m1 = mn1;
        float ls0 = 0.f, ls1 = 0.f;
#pragma unroll
        for (int nt = 0; nt < 8; nt++) {
            s[nt][0] = fexp(s[nt][0] - mn0); ls0 += s[nt][0];
            s[nt][1] = fexp(s[nt][1] - mn0); ls0 += s[nt][1];
            s[nt][2] = fexp(s[nt][2] - mn1); ls1 += s[nt][2];
            s[nt][3] = fexp(s[nt][3] - mn1); ls1 += s[nt][3];
        }
        ls0 += __shfl_xor_sync(0xffffffffu, ls0, 1);
        ls0 += __shfl_xor_sync(0xffffffffu, ls0, 2);
        ls1 += __shfl_xor_sync(0xffffffffu, ls1, 1);
        ls1 += __shfl_xor_sync(0xffffffffu, ls1, 2);
        l0 = l0 * cr0 + ls0;
        l1 = l1 * cr1 + ls1;
#pragma unroll
        for (int j = 0; j < 8; j++) {
            o[j][0] *= cr0; o[j][1] *= cr0; o[j][2] *= cr1; o[j][3] *= cr1;
        }

        // ---- O += Phi*Vhi + Plo*Vhi + Phi*Vlo ----
#pragma unroll
        for (int kt = 0; kt < 4; kt++) {
            u32 ph[4], pl[4];
            ph[0] = cvt_bf16x2(s[2 * kt][1],     s[2 * kt][0]);
            ph[1] = cvt_bf16x2(s[2 * kt][3],     s[2 * kt][2]);
            ph[2] = cvt_bf16x2(s[2 * kt + 1][1], s[2 * kt + 1][0]);
            ph[3] = cvt_bf16x2(s[2 * kt + 1][3], s[2 * kt + 1][2]);
            pl[0] = cvt_bf16x2(s[2 * kt][1] - bf_hi(ph[0]),     s[2 * kt][0] - bf_lo(ph[0]));
            pl[1] = cvt_bf16x2(s[2 * kt][3] - bf_hi(ph[1]),     s[2 * kt][2] - bf_lo(ph[1]));
            pl[2] = cvt_bf16x2(s[2 * kt + 1][1] - bf_hi(ph[2]), s[2 * kt + 1][0] - bf_lo(ph[2]));
            pl[3] = cvt_bf16x2(s[2 * kt + 1][3] - bf_hi(ph[3]), s[2 * kt + 1][2] - bf_lo(ph[3]));
#pragma unroll
            for (int np = 0; np < 4; np++) {
                const int off = b_off + np * (16 * 144) + kt * 32;
                u32 v0, v1, v2, v3, w0, w1, w2, w3;
                ldm4(v0, v1, v2, v3, sVhi + off);
                mma16816(o[2 * np],     ph, v0, v1);
                mma16816(o[2 * np + 1], ph, v2, v3);
                mma16816(o[2 * np],     pl, v0, v1);
                mma16816(o[2 * np + 1], pl, v2, v3);
                ldm4(w0, w1, w2, w3, sVlo + off);
                mma16816(o[2 * np],     ph, w0, w1);
                mma16816(o[2 * np + 1], ph, w2, w3);
            }
        }
    }

    // ---- epilogue: O/l -> bf16 hi/lo -> y3 [hi|hi|lo] ----
    const float inv0 = 1.f / l0, inv1 = 1.f / l1;
    const int tg0 = qb * 64 + 16 * wid + g;
    const size_t m0i = (size_t)(b * Td + tg0) * K3;
    const size_t m1i = (size_t)(b * Td + tg0 + 8) * K3;
#pragma unroll
    for (int nt = 0; nt < 8; nt++) {
        const int col = h * 64 + 8 * nt + 2 * t;
        {
            const float f0 = o[nt][0] * inv0, f1 = o[nt][1] * inv0;
            const u32 hi = cvt_bf16x2(f1, f0);
            const u32 lo = cvt_bf16x2(f1 - bf_hi(hi), f0 - bf_lo(hi));
            *(u32*)(y3 + m0i + col)        = hi;
            *(u32*)(y3 + m0i + col + 1024) = hi;
            *(u32*)(y3 + m0i + col + 2048) = lo;
        }
        {
            const float f2 = o[nt][2] * inv1, f3 = o[nt][3] * inv1;
            const u32 hi = cvt_bf16x2(f3, f2);
            const u32 lo = cvt_bf16x2(f3 - bf_hi(hi), f2 - bf_lo(hi));
            *(u32*)(y3 + m1i + col)        = hi;
            *(u32*)(y3 + m1i + col + 1024) = hi;
            *(u32*)(y3 + m1i + col + 2048) = lo;
        }
    }
}

// ---------------------------------------------------------------------------
extern "C" void kernel_launch(void* const* d_in, const int* in_sizes, int n_in,
                              void* d_out, int out_size)
{
    const float* x      = (const float*)d_in[0];
    const float* w_attn = (const float*)d_in[1];
    const float* w_proj = (const float*)d_in[2];
    float* out = (float*)d_out;

    float* qkv;
    __nv_bfloat16 *x3, *y3, *wa3, *wp3;
    cudaGetSymbolAddress((void**)&qkv, g_qkv);
    cudaGetSymbolAddress((void**)&x3, g_x3);
    cudaGetSymbolAddress((void**)&y3, g_y3);
    cudaGetSymbolAddress((void**)&wa3, g_wa3);
    cudaGetSymbolAddress((void**)&wp3, g_wp3);

    const int gemm_smem = 4 * GBUF * 2;   // 73728 B
    cudaFuncSetAttribute(gemm_mma, cudaFuncAttributeMaxDynamicSharedMemorySize, gemm_smem);

    // conversions
    split_rows3<<<(Mtot * Cd / 4 + 255) / 256, 256>>>(x, x3, Mtot, Cd);
    split_tr3<<<(Cd * 3 * Cd + 255) / 256, 256>>>(w_attn, wa3, Cd, 3 * Cd);
    split_tr3<<<(Cd * Cd + 255) / 256, 256>>>(w_proj, wp3, Cd, Cd);

    // 1) QKV GEMM
    dim3 g1(3 * Cd / 128, Mtot / 128);    // (24, 64)
    gemm_mma<<<g1, 256, gemm_smem>>>(x3, wa3, qkv, 3 * Cd);

    // 2) reformat + split for attention
    dim3 gp(Td / 64, Bd * Hd);            // (32, 64)
    prep_attn<<<gp, 256>>>(qkv);

    // 3) causal attention -> y3
    dim3 g2(Td / 64, Bd * Hd);
    flash_mma<<<g2, 128>>>(y3);

    // 4) proj GEMM
    dim3 g3(Cd / 128, Mtot / 128);        // (8, 64)
    gemm_mma<<<g3, 256, gemm_smem>>>(y3, wp3, out, Cd);
}

// round 5
// speedup vs baseline: 4.7896x; 1.0571x over previous
#include <cuda_runtime.h>
#include <cuda_bf16.h>
#include <math.h>
#include <stdint.h>

#define Bd 4
#define Td 2048
#define Cd 1024
#define Hd 16
#define DHd 64
#define Mtot (Bd * Td)      // 8192
#define K3 (3 * Cd)         // 3072 split-K: A=[hi|hi|lo], B=[hi|lo|hi]

typedef uint32_t u32;

// ---- scratch (__device__ globals; allocation-free rule) --------------------
__device__ float g_qkv[(size_t)Mtot * 3 * Cd];                 // fp32 [8192,3072]
__device__ __nv_bfloat16 g_x3[(size_t)Mtot * K3];
__device__ __nv_bfloat16 g_y3[(size_t)Mtot * K3];
__device__ __nv_bfloat16 g_wa3[(size_t)(3 * Cd) * K3];
__device__ __nv_bfloat16 g_wp3[(size_t)Cd * K3];
__device__ __nv_bfloat16 g_qhi[(size_t)Bd * Hd * Td * DHd];
__device__ __nv_bfloat16 g_qlo[(size_t)Bd * Hd * Td * DHd];
__device__ __nv_bfloat16 g_khi[(size_t)Bd * Hd * Td * DHd];
__device__ __nv_bfloat16 g_klo[(size_t)Bd * Hd * Td * DHd];
__device__ __nv_bfloat16 g_vthi[(size_t)Bd * Hd * DHd * Td];
__device__ __nv_bfloat16 g_vtlo[(size_t)Bd * Hd * DHd * Td];

// ---- helpers ----------------------------------------------------------------
__device__ __forceinline__ u32 smem_u32(const void* p) {
    u32 a;
    asm("{ .reg .u64 t; cvta.to.shared.u64 t, %1; cvt.u32.u64 %0, t; }" : "=r"(a) : "l"(p));
    return a;
}
__device__ __forceinline__ void ldm4(u32& r0, u32& r1, u32& r2, u32& r3, u32 addr) {
    asm volatile("ldmatrix.sync.aligned.m8n8.x4.shared.b16 {%0,%1,%2,%3}, [%4];"
                 : "=r"(r0), "=r"(r1), "=r"(r2), "=r"(r3) : "r"(addr));
}
__device__ __forceinline__ void mma16816(float* d, const u32* a, u32 b0, u32 b1) {
    asm volatile(
        "mma.sync.aligned.m16n8k16.row.col.f32.bf16.bf16.f32 "
        "{%0,%1,%2,%3}, {%4,%5,%6,%7}, {%8,%9}, {%0,%1,%2,%3};"
        : "+f"(d[0]), "+f"(d[1]), "+f"(d[2]), "+f"(d[3])
        : "r"(a[0]), "r"(a[1]), "r"(a[2]), "r"(a[3]), "r"(b0), "r"(b1));
}
__device__ __forceinline__ void cpa16(u32 dst, const void* src) {
    asm volatile("cp.async.cg.shared.global [%0], [%1], 16;" :: "r"(dst), "l"(src) : "memory");
}
__device__ __forceinline__ void cpa_commit() {
    asm volatile("cp.async.commit_group;" ::: "memory");
}
__device__ __forceinline__ u32 cvt_bf16x2(float hi, float lo) {
    u32 r;
    asm("cvt.rn.bf16x2.f32 %0, %1, %2;" : "=r"(r) : "f"(hi), "f"(lo));
    return r;
}
__device__ __forceinline__ float bf_lo(u32 r) { return __uint_as_float(r << 16); }
__device__ __forceinline__ float bf_hi(u32 r) { return __uint_as_float(r & 0xFFFF0000u); }

// FFMA-only exp (rel err ~1e-7), valid for x <= 0
__device__ __forceinline__ float fexp(float x) {
    x = fmaxf(x, -80.f);
    float t  = fmaf(x, 1.4426950408889634f, 12582912.0f);
    float fi = t - 12582912.0f;
    float f  = fmaf(x, 1.4426950408889634f, -fi);
    float p  = 0.00015403530393381609f;
    p = fmaf(p, f, 0.0013333558146428443f);
    p = fmaf(p, f, 0.009618129107628477f);
    p = fmaf(p, f, 0.05550410866482158f);
    p = fmaf(p, f, 0.2402265069591007f);
    p = fmaf(p, f, 0.6931471805599453f);
    p = fmaf(p, f, 1.0f);
    int ei = __float_as_int(t) - 0x4B400000;
    return __uint_as_float(__float_as_int(p) + (ei << 23));
}

// ---------------------------------------------------------------------------
// fp32 -> bf16x3 split conversions
// ---------------------------------------------------------------------------
__global__ void split_rows3(const float* __restrict__ in, __nv_bfloat16* __restrict__ out,
                            int R, int Cc)
{
    int idx = blockIdx.x * blockDim.x + threadIdx.x;
    int total = R * Cc / 4;
    if (idx >= total) return;
    int c = (idx % (Cc / 4)) * 4;
    int r = idx / (Cc / 4);
    float4 v = *(const float4*)(in + (size_t)r * Cc + c);
    __nv_bfloat162 h0 = __floats2bfloat162_rn(v.x, v.y);
    __nv_bfloat162 h1 = __floats2bfloat162_rn(v.z, v.w);
    __nv_bfloat162 l0 = __floats2bfloat162_rn(v.x - __bfloat162float(h0.x),
                                              v.y - __bfloat162float(h0.y));
    __nv_bfloat162 l1 = __floats2bfloat162_rn(v.z - __bfloat162float(h1.x),
                                              v.w - __bfloat162float(h1.y));
    __nv_bfloat16* o = out + (size_t)r * (3 * Cc) + c;
    uint2 hv = make_uint2(*(u32*)&h0, *(u32*)&h1);
    uint2 lv = make_uint2(*(u32*)&l0, *(u32*)&l1);
    *(uint2*)(o)          = hv;
    *(uint2*)(o + Cc)     = hv;
    *(uint2*)(o + 2 * Cc) = lv;
}

// w [K][N] -> out [N][3K] = [hi | lo | hi]; coalesced via 32x32 smem tiles.
// grid (N/32, K/32), 256 threads.
__global__ void __launch_bounds__(256) split_tr3(
    const float* __restrict__ w, __nv_bfloat16* __restrict__ out, int K, int N)
{
    __shared__ float tile[32][33];
    const int tid = threadIdx.x;
    const int n0 = blockIdx.x * 32, k0 = blockIdx.y * 32;
    {
        const int r = tid >> 3, c = (tid & 7) * 4;   // k-row, n-col
        float4 v = *(const float4*)(w + (size_t)(k0 + r) * N + n0 + c);
        tile[r][c] = v.x; tile[r][c + 1] = v.y; tile[r][c + 2] = v.z; tile[r][c + 3] = v.w;
    }
    __syncthreads();
    {
        const int n = tid >> 3, c = (tid & 7) * 4;   // n-row of out, k-col
        u32 hw[2], lw[2];
#pragma unroll
        for (int p = 0; p < 2; p++) {
            float v0 = tile[c + 2 * p][n], v1 = tile[c + 2 * p + 1][n];
            hw[p] = cvt_bf16x2(v1, v0);
            lw[p] = cvt_bf16x2(v1 - bf_hi(hw[p]), v0 - bf_lo(hw[p]));
        }
        __nv_bfloat16* o = out + (size_t)(n0 + n) * (3 * K) + k0 + c;
        *(uint2*)(o)         = make_uint2(hw[0], hw[1]);
        *(uint2*)(o + K)     = make_uint2(lw[0], lw[1]);
        *(uint2*)(o + 2 * K) = make_uint2(hw[0], hw[1]);
    }
}

// ---------------------------------------------------------------------------
// GEMM (HMMA): C[M,Nout] fp32 = A3[M,3072] @ Bt3[Nout,3072]^T
// CTA 128x128, 4 warps (2m x 2n), warp 64x64. KC=64, cp.async double-buffered.
// smem rows padded to 72 bf16 (144B).
// ---------------------------------------------------------------------------
#define GROWB 144                    // bytes per smem row
#define GBUFB (128 * GROWB)          // 18432 B per operand per buffer
__global__ void __launch_bounds__(128) gemm_mma(
    const __nv_bfloat16* __restrict__ A, const __nv_bfloat16* __restrict__ Bt,
    float* __restrict__ C, int Nout)
{
    extern __shared__ __align__(16) char sm[];
    const u32 sA = smem_u32(sm);             // [2][128][144B]
    const u32 sB = sA + 2 * GBUFB;           // [2][128][144B]

    const int tid = threadIdx.x, wid = tid >> 5, lane = tid & 31;
    const int wm = wid >> 1, wn = wid & 1;
    const int g = lane >> 2, t = lane & 3;
    const int row0 = blockIdx.y * 128, col0 = blockIdx.x * 128;

    // cp.async mapping: lr = tid>>3 (0..15), lc = (tid&7)*8 elems; 8 rows apart 16
    const int lr = tid >> 3, lce = (tid & 7) * 8;
    const __nv_bfloat16* Ag = A + (size_t)(row0 + lr) * K3 + lce;
    const __nv_bfloat16* Bg = Bt + (size_t)(col0 + lr) * K3 + lce;
    const u32 da0 = sA + lr * GROWB + (tid & 7) * 16;
    const u32 db0 = sB + lr * GROWB + (tid & 7) * 16;

    float acc[4][8][4];
#pragma unroll
    for (int i = 0; i < 4; i++)
#pragma unroll
        for (int j = 0; j < 8; j++)
#pragma unroll
            for (int r = 0; r < 4; r++) acc[i][j][r] = 0.f;

    const int a_row_off = (64 * wm + (lane & 15)) * GROWB + ((lane >> 4) << 4);
    const int b_row_off = (64 * wn + (lane & 7) + 8 * ((lane >> 4) & 1)) * GROWB
                        + 16 * ((lane >> 3) & 1);

    // prefetch chunk 0
#pragma unroll
    for (int i = 0; i < 8; i++) {
        cpa16(da0 + i * 16 * GROWB, Ag + (size_t)(16 * i) * K3);
        cpa16(db0 + i * 16 * GROWB, Bg + (size_t)(16 * i) * K3);
    }
    cpa_commit();

    for (int kc = 0; kc < 48; kc++) {
        const int buf = kc & 1;
        if (kc < 47) {
            const int nb = buf ^ 1;
            const size_t ko = (size_t)(kc + 1) * 64;
#pragma unroll
            for (int i = 0; i < 8; i++) {
                cpa16(da0 + nb * GBUFB + i * 16 * GROWB, Ag + (size_t)(16 * i) * K3 + ko);
                cpa16(db0 + nb * GBUFB + i * 16 * GROWB, Bg + (size_t)(16 * i) * K3 + ko);
            }
            cpa_commit();
            asm volatile("cp.async.wait_group 1;" ::: "memory");
        } else {
            asm volatile("cp.async.wait_group 0;" ::: "memory");
        }
        __syncthreads();

        const u32 abase = sA + buf * GBUFB + a_row_off;
        const u32 bbase = sB + buf * GBUFB + b_row_off;
#pragma unroll
        for (int kt = 0; kt < 4; kt++) {
            u32 af[4][4], bf[4][4];
#pragma unroll
            for (int mt = 0; mt < 4; mt++)
                ldm4(af[mt][0], af[mt][1], af[mt][2], af[mt][3],
                     abase + mt * (16 * GROWB) + kt * 32);
#pragma unroll
            for (int np = 0; np < 4; np++)
                ldm4(bf[np][0], bf[np][1], bf[np][2], bf[np][3],
                     bbase + np * (16 * GROWB) + kt * 32);
#pragma unroll
            for (int mt = 0; mt < 4; mt++)
#pragma unroll
                for (int np = 0; np < 4; np++) {
                    mma16816(acc[mt][2 * np],     af[mt], bf[np][0], bf[np][1]);
                    mma16816(acc[mt][2 * np + 1], af[mt], bf[np][2], bf[np][3]);
                }
        }
        __syncthreads();
    }

    // epilogue
#pragma unroll
    for (int mt = 0; mt < 4; mt++) {
        const int r0 = row0 + 64 * wm + 16 * mt + g;
#pragma unroll
        for (int nt = 0; nt < 8; nt++) {
            const int col = col0 + 64 * wn + 8 * nt + 2 * t;
            *(float2*)(C + (size_t)r0 * Nout + col)       = make_float2(acc[mt][nt][0], acc[mt][nt][1]);
            *(float2*)(C + (size_t)(r0 + 8) * Nout + col) = make_float2(acc[mt][nt][2], acc[mt][nt][3]);
        }
    }
}

// ---------------------------------------------------------------------------
// prep_attn: g_qkv fp32 -> Qhi/Qlo/Khi/Klo [bh][t][64] (Q pre-scaled by 1/8),
//            Vthi/Vtlo [bh][d][t] (transposed via smem).
// ---------------------------------------------------------------------------
__global__ void __launch_bounds__(256) prep_attn(const float* __restrict__ qkv)
{
    __shared__ __nv_bfloat16 tvhi[64][72];
    __shared__ __nv_bfloat16 tvlo[64][72];
    const int tid = threadIdx.x;
    const int tb = blockIdx.x, bh = blockIdx.y;
    const int b = bh >> 4, h = bh & 15;

#pragma unroll
    for (int i = 0; i < 4; i++) {
        const int u = tid + 256 * i;
        const int tr = u >> 4;
        const int d4 = (u & 15) * 4;
        const int tg = tb * 64 + tr;
        const size_t base = ((size_t)(b * Td + tg)) * 3072 + h * 64 + d4;
        float4 q = *(const float4*)(qkv + base);
        float4 k = *(const float4*)(qkv + base + 1024);
        float4 v = *(const float4*)(qkv + base + 2048);
        q.x *= 0.125f; q.y *= 0.125f; q.z *= 0.125f; q.w *= 0.125f;

        const size_t qidx = ((size_t)bh * Td + tg) * 64 + d4;
        __nv_bfloat162 qh0 = __floats2bfloat162_rn(q.x, q.y);
        __nv_bfloat162 qh1 = __floats2bfloat162_rn(q.z, q.w);
        __nv_bfloat162 ql0 = __floats2bfloat162_rn(q.x - __bfloat162float(qh0.x), q.y - __bfloat162float(qh0.y));
        __nv_bfloat162 ql1 = __floats2bfloat162_rn(q.z - __bfloat162float(qh1.x), q.w - __bfloat162float(qh1.y));
        *(uint2*)(g_qhi + qidx) = make_uint2(*(u32*)&qh0, *(u32*)&qh1);
        *(uint2*)(g_qlo + qidx) = make_uint2(*(u32*)&ql0, *(u32*)&ql1);

        __nv_bfloat162 kh0 = __floats2bfloat162_rn(k.x, k.y);
        __nv_bfloat162 kh1 = __floats2bfloat162_rn(k.z, k.w);
        __nv_bfloat162 kl0 = __floats2bfloat162_rn(k.x - __bfloat162float(kh0.x), k.y - __bfloat162float(kh0.y));
        __nv_bfloat162 kl1 = __floats2bfloat162_rn(k.z - __bfloat162float(kh1.x), k.w - __bfloat162float(kh1.y));
        *(uint2*)(g_khi + qidx) = make_uint2(*(u32*)&kh0, *(u32*)&kh1);
        *(uint2*)(g_klo + qidx) = make_uint2(*(u32*)&kl0, *(u32*)&kl1);

        float vv[4] = {v.x, v.y, v.z, v.w};
#pragma unroll
        for (int j = 0; j < 4; j++) {
            __nv_bfloat16 hi = __float2bfloat16(vv[j]);
            __nv_bfloat16 lo = __float2bfloat16(vv[j] - __bfloat162float(hi));
            tvhi[d4 + j][tr] = hi;
            tvlo[d4 + j][tr] = lo;
        }
    }
    __syncthreads();
#pragma unroll
    for (int i = 0; i < 2; i++) {
        const int u = tid + 256 * i;
        const int d = u >> 3;
        const int tc = (u & 7) * 8;
        const size_t vidx = ((size_t)bh * 64 + d) * Td + tb * 64 + tc;
        *(uint4*)(g_vthi + vidx) = *(uint4*)&tvhi[d][tc];
        *(uint4*)(g_vtlo + vidx) = *(uint4*)&tvlo[d][tc];
    }
}

// ---------------------------------------------------------------------------
// flash_mma: causal attention, HMMA bf16 hi/lo split. 128 threads, 4 warps.
// ---------------------------------------------------------------------------
__global__ void __launch_bounds__(128) flash_mma(__nv_bfloat16* __restrict__ y3)
{
    __shared__ __align__(16) __nv_bfloat16 s_t[4][64 * 72];
    const int tid = threadIdx.x, wid = tid >> 5, lane = tid & 31;
    const int g = lane >> 2, t = lane & 3;
    const int qb = gridDim.x - 1 - blockIdx.x;
    const int bh = blockIdx.y;
    const int b = bh >> 4, h = bh & 15;

    const size_t qkbase = (size_t)bh * Td * 64;
    const size_t vtbase = (size_t)bh * 64 * Td;

    const u32 s0 = smem_u32(s_t);
    const u32 sKhi = s0, sKlo = s0 + 9216, sVhi = s0 + 18432, sVlo = s0 + 27648;

    const int a_off = (16 * wid + (lane & 15)) * 144 + ((lane >> 4) << 4);
    const int b_off = ((lane & 7) + 8 * ((lane >> 4) & 1)) * 144 + 16 * ((lane >> 3) & 1);

#pragma unroll
    for (int i = 0; i < 4; i++) {
        const int u = tid + 128 * i;
        const int r = u >> 3, c = (u & 7) * 8;
        const size_t gq = qkbase + (size_t)(qb * 64 + r) * 64 + c;
        *(uint4*)&s_t[0][r * 72 + c] = *(const uint4*)(g_qhi + gq);
        *(uint4*)&s_t[1][r * 72 + c] = *(const uint4*)(g_qlo + gq);
    }
    __syncthreads();
    u32 qh[4][4], ql[4][4];
#pragma unroll
    for (int kt = 0; kt < 4; kt++) {
        ldm4(qh[kt][0], qh[kt][1], qh[kt][2], qh[kt][3], sKhi + a_off + kt * 32);
        ldm4(ql[kt][0], ql[kt][1], ql[kt][2], ql[kt][3], sKlo + a_off + kt * 32);
    }

    float o[8][4];
#pragma unroll
    for (int j = 0; j < 8; j++)
#pragma unroll
        for (int r = 0; r < 4; r++) o[j][r] = 0.f;
    float m0 = -1e30f, m1 = -1e30f, l0 = 0.f, l1 = 0.f;

    for (int kb = 0; kb <= qb; kb++) {
        __syncthreads();
#pragma unroll
        for (int i = 0; i < 4; i++) {
            const int u = tid + 128 * i;
            const int r = u >> 3, c = (u & 7) * 8;
            const size_t gk = qkbase + (size_t)(kb * 64 + r) * 64 + c;
            const size_t gv = vtbase + (size_t)r * Td + kb * 64 + c;
            *(uint4*)&s_t[0][r * 72 + c] = *(const uint4*)(g_khi + gk);
            *(uint4*)&s_t[1][r * 72 + c] = *(const uint4*)(g_klo + gk);
            *(uint4*)&s_t[2][r * 72 + c] = *(const uint4*)(g_vthi + gv);
            *(uint4*)&s_t[3][r * 72 + c] = *(const uint4*)(g_vtlo + gv);
        }
        __syncthreads();

        float s[8][4];
#pragma unroll
        for (int j = 0; j < 8; j++)
#pragma unroll
            for (int r = 0; r < 4; r++) s[j][r] = 0.f;
#pragma unroll
        for (int np = 0; np < 4; np++) {
#pragma unroll
            for (int kt = 0; kt < 4; kt++) {
                const int off = b_off + np * (16 * 144) + kt * 32;
                u32 h0, h1, h2, h3, e0, e1, e2, e3;
                ldm4(h0, h1, h2, h3, sKhi + off);
                mma16816(s[2 * np],     qh[kt], h0, h1);
                mma16816(s[2 * np + 1], qh[kt], h2, h3);
                mma16816(s[2 * np],     ql[kt], h0, h1);
                mma16816(s[2 * np + 1], ql[kt], h2, h3);
                ldm4(e0, e1, e2, e3, sKlo + off);
                mma16816(s[2 * np],     qh[kt], e0, e1);
                mma16816(s[2 * np + 1], qh[kt], e2, e3);
            }
        }

        if (kb == qb) {
            const int qg0 = qb * 64 + 16 * wid + g;
            const int qg1 = qg0 + 8;
#pragma unroll
            for (int nt = 0; nt < 8; nt++) {
                const int kg = kb * 64 + 8 * nt + 2 * t;
                if (kg > qg0)     s[nt][0] = -1e30f;
                if (kg + 1 > qg0) s[nt][1] = -1e30f;
                if (kg > qg1)     s[nt][2] = -1e30f;
                if (kg + 1 > qg1) s[nt][3] = -1e30f;
            }
        }

        float ml0 = -1e30f, ml1 = -1e30f;
#pragma unroll
        for (int nt = 0; nt < 8; nt++) {
            ml0 = fmaxf(ml0, fmaxf(s[nt][0], s[nt][1]));
            ml1 = fmaxf(ml1, fmaxf(s[nt][2], s[nt][3]));
        }
        ml0 = fmaxf(ml0, __shfl_xor_sync(0xffffffffu, ml0, 1));
        ml0 = fmaxf(ml0, __shfl_xor_sync(0xffffffffu, ml0, 2));
        ml1 = fmaxf(ml1, __shfl_xor_sync(0xffffffffu, ml1, 1));
        ml1 = fmaxf(ml1, __shfl_xor_sync(0xffffffffu, ml1, 2));
        const float mn0 = fmaxf(m0, ml0), mn1 = fmaxf(m1, ml1);
        const float cr0 = fexp(m0 - mn0), cr1 = fexp(m1 - mn1);
        m0 = mn0; m1 = mn1;
        float ls0 = 0.f, ls1 = 0.f;
#pragma unroll
        for (int nt = 0; nt < 8; nt++) {
            s[nt][0] = fexp(s[nt][0] - mn0); ls0 += s[nt][0];
            s[nt][1] = fexp(s[nt][1] - mn0); ls0 += s[nt][1];
            s[nt][2] = fexp(s[nt][2] - mn1); ls1 += s[nt][2];
            s[nt][3] = fexp(s[nt][3] - mn1); ls1 += s[nt][3];
        }
        ls0 += __shfl_xor_sync(0xffffffffu, ls0, 1);
        ls0 += __shfl_xor_sync(0xffffffffu, ls0, 2);
        ls1 += __shfl_xor_sync(0xffffffffu, ls1, 1);
        ls1 += __shfl_xor_sync(0xffffffffu, ls1, 2);
        l0 = l0 * cr0 + ls0;
        l1 = l1 * cr1 + ls1;
#pragma unroll
        for (int j = 0; j < 8; j++) {
            o[j][0] *= cr0; o[j][1] *= cr0; o[j][2] *= cr1; o[j][3] *= cr1;
        }

#pragma unroll
        for (int kt = 0; kt < 4; kt++) {
            u32 ph[4], pl[4];
            ph[0] = cvt_bf16x2(s[2 * kt][1],     s[2 * kt][0]);
            ph[1] = cvt_bf16x2(s[2 * kt][3],     s[2 * kt][2]);
            ph[2] = cvt_bf16x2(s[2 * kt + 1][1], s[2 * kt + 1][0]);
            ph[3] = cvt_bf16x2(s[2 * kt + 1][3], s[2 * kt + 1][2]);
            pl[0] = cvt_bf16x2(s[2 * kt][1] - bf_hi(ph[0]),     s[2 * kt][0] - bf_lo(ph[0]));
            pl[1] = cvt_bf16x2(s[2 * kt][3] - bf_hi(ph[1]),     s[2 * kt][2] - bf_lo(ph[1]));
            pl[2] = cvt_bf16x2(s[2 * kt + 1][1] - bf_hi(ph[2]), s[2 * kt + 1][0] - bf_lo(ph[2]));
            pl[3] = cvt_bf16x2(s[2 * kt + 1][3] - bf_hi(ph[3]), s[2 * kt + 1][2] - bf_lo(ph[3]));
#pragma unroll
            for (int np = 0; np < 4; np++) {
                const int off = b_off + np * (16 * 144) + kt * 32;
                u32 v0, v1, v2, v3, w0, w1, w2, w3;
                ldm4(v0, v1, v2, v3, sVhi + off);
                mma16816(o[2 * np],     ph, v0, v1);
                mma16816(o[2 * np + 1], ph, v2, v3);
                mma16816(o[2 * np],     pl, v0, v1);
                mma16816(o[2 * np + 1], pl, v2, v3);
                ldm4(w0, w1, w2, w3, sVlo + off);
                mma16816(o[2 * np],     ph, w0, w1);
                mma16816(o[2 * np + 1], ph, w2, w3);
            }
        }
    }

    const float inv0 = 1.f / l0, inv1 = 1.f / l1;
    const int tg0 = qb * 64 + 16 * wid + g;
    const size_t m0i = (size_t)(b * Td + tg0) * K3;
    const size_t m1i = (size_t)(b * Td + tg0 + 8) * K3;
#pragma unroll
    for (int nt = 0; nt < 8; nt++) {
        const int col = h * 64 + 8 * nt + 2 * t;
        {
            const float f0 = o[nt][0] * inv0, f1 = o[nt][1] * inv0;
            const u32 hi = cvt_bf16x2(f1, f0);
            const u32 lo = cvt_bf16x2(f1 - bf_hi(hi), f0 - bf_lo(hi));
            *(u32*)(y3 + m0i + col)        = hi;
            *(u32*)(y3 + m0i + col + 1024) = hi;
            *(u32*)(y3 + m0i + col + 2048) = lo;
        }
        {
            const float f2 = o[nt][2] * inv1, f3 = o[nt][3] * inv1;
            const u32 hi = cvt_bf16x2(f3, f2);
            const u32 lo = cvt_bf16x2(f3 - bf_hi(hi), f2 - bf_lo(hi));
            *(u32*)(y3 + m1i + col)        = hi;
            *(u32*)(y3 + m1i + col + 1024) = hi;
            *(u32*)(y3 + m1i + col + 2048) = lo;
        }
    }
}

// ---------------------------------------------------------------------------
extern "C" void kernel_launch(void* const* d_in, const int* in_sizes, int n_in,
                              void* d_out, int out_size)
{
    const float* x      = (const float*)d_in[0];
    const float* w_attn = (const float*)d_in[1];
    const float* w_proj = (const float*)d_in[2];
    float* out = (float*)d_out;

    float* qkv;
    __nv_bfloat16 *x3, *y3, *wa3, *wp3;
    cudaGetSymbolAddress((void**)&qkv, g_qkv);
    cudaGetSymbolAddress((void**)&x3, g_x3);
    cudaGetSymbolAddress((void**)&y3, g_y3);
    cudaGetSymbolAddress((void**)&wa3, g_wa3);
    cudaGetSymbolAddress((void**)&wp3, g_wp3);

    const int gemm_smem = 4 * GBUFB;   // 73728 B
    cudaFuncSetAttribute(gemm_mma, cudaFuncAttributeMaxDynamicSharedMemorySize, gemm_smem);

    split_rows3<<<(Mtot * Cd / 4 + 255) / 256, 256>>>(x, x3, Mtot, Cd);
    split_tr3<<<dim3(3 * Cd / 32, Cd / 32), 256>>>(w_attn, wa3, Cd, 3 * Cd);
    split_tr3<<<dim3(Cd / 32, Cd / 32), 256>>>(w_proj, wp3, Cd, Cd);

    dim3 g1(3 * Cd / 128, Mtot / 128);    // (24, 64)
    gemm_mma<<<g1, 128, gemm_smem>>>(x3, wa3, qkv, 3 * Cd);

    dim3 gp(Td / 64, Bd * Hd);
    prep_attn<<<gp, 256>>>(qkv);

    dim3 g2(Td / 64, Bd * Hd);
    flash_mma<<<g2, 128>>>(y3);

    dim3 g3(Cd / 128, Mtot / 128);        // (8, 64)
    gemm_mma<<<g3, 128, gemm_smem>>>(y3, wp3, out, Cd);
}